// round 2
// baseline (speedup 1.0000x reference)
#include <cuda_runtime.h>
#include <cstdint>

// NeuralHMM forward algorithm, B=32, T=4096, K=16.
// 3-phase chunked parallel scan in LINEAR probability space (valid because the
// reference clips A to 1e-10 before log, which floors all alphas at ~1e-12).
//
// Phase 1 (k_chunkmats): per chunk of 64 timesteps, compose the 16x16 linear
//   transfer matrix  P = prod_t ( clip(A_t,1e-10) * diag(exp(em_t)) ),
//   tridiagonal + uniform 1e-10 background, with periodic max-rescaling.
//   Also writes the normalized A tensor output (fused: overlaps 134MB write).
// Phase 2 (k_scan): per batch, sequential scan over 64 chunk matrices to get
//   the normalized alpha carried into each chunk.
// Phase 3 (k_replay): per chunk, replay the 64 steps exactly (tridiag matvec,
//   background, per-step normalization) writing beliefs/log_beliefs/log_norms.

#define FULLM 0xffffffffu

constexpr int B_ = 32, T_ = 4096, K_ = 16, C_ = 64, NCH = T_ / C_;   // NCH = 64
constexpr int NCHUNKS = B_ * NCH;                                     // 2048
constexpr float RHO = 0.001f;
constexpr float CLIPV = 1e-10f;

__device__ __align__(16) float g_chunkM[NCHUNKS][K_][K_]; // [chunk][k][i] = M[i][k] (column-major)
__device__ __align__(16) float g_carry[NCHUNKS][K_];      // normalized alpha entering chunk j (j>=1)

// output layout (floats)
constexpr size_t N_BTK = (size_t)B_ * T_ * K_;
constexpr size_t N_BT  = (size_t)B_ * T_;
constexpr size_t OFF_LB = N_BTK;
constexpr size_t OFF_LZ = 2 * N_BTK;
constexpr size_t OFF_A  = 2 * N_BTK + N_BT;

// ---------------------------------------------------------------------------
// Phase 1: chunk transfer matrices + A output. 2 chunks per warp (half-warps).
// Lane owns row i of the 16x16 running product.
// ---------------------------------------------------------------------------
__global__ __launch_bounds__(128) void k_chunkmats(
    const float* __restrict__ em, const float* __restrict__ bp,
    float* __restrict__ out)
{
    const int gwarp = (blockIdx.x * blockDim.x + threadIdx.x) >> 5;
    const int lane  = threadIdx.x & 31;
    const int i     = lane & 15;
    const int chunk = gwarp * 2 + (lane >> 4);
    if (chunk >= NCHUNKS) return;
    const unsigned hm = 0xffffu << (lane & 16);   // half-warp mask
    const int b  = chunk / NCH;
    const int j  = chunk - b * NCH;
    const int t0 = j * C_;

    float* __restrict__ A_out = out + OFF_A;

    float m[K_];
#pragma unroll
    for (int k = 0; k < K_; k++) m[k] = (k == i) ? 1.0f : 0.0f;
    float rs = 1.0f;   // running row-sum of row i

    const size_t bt0 = (size_t)b * T_ + t0;
    const float* embase = em + bt0 * K_;
    const float* bpbase = bp + bt0;
    float* Abase = A_out + bt0 * (size_t)(K_ * K_);

    for (int s = 0; s < C_; s++) {
        const float bpv = __ldg(bpbase + s);
        const float eta = fminf(fmaxf(0.02f + 0.33f * bpv, 0.001f), 0.95f);
        const float d0  = 1.0f - eta;
        const float dm  = fmaxf((1.0f - eta) - RHO, 0.01f);
        const float d15 = 1.0f - RHO;
        const float rs0  = fmaxf(d0 + eta, 1e-8f);
        const float rsm  = fmaxf((RHO + dm) + eta, 1e-8f);
        const float rs15 = fmaxf(RHO + d15, 1e-8f);
        const float inv0  = __fdividef(1.0f, rs0);
        const float invm  = __fdividef(1.0f, rsm);
        const float inv15 = __fdividef(1.0f, rs15);

        // ---- write A row i (normalized; zeros stay zero) ----
        {
            const float invr = (i == 0) ? inv0 : (i == 15 ? inv15 : invm);
            const float dv = ((i == 0) ? d0 : (i == 15 ? d15 : dm)) * invr;
            const float ev = eta * invr;   // at column i+1 (i<15)
            const float rv = RHO * invr;   // at column i-1 (i>0)
            float w[16];
#pragma unroll
            for (int q = 0; q < 16; q++) {
                float v = 0.0f;
                v = (q == i)     ? dv : v;
                v = (q == i + 1) ? ev : v;
                v = (q == i - 1) ? rv : v;
                w[q] = v;
            }
            float4* dst = reinterpret_cast<float4*>(Abase + (size_t)s * 256 + i * 16);
            dst[0] = make_float4(w[0],  w[1],  w[2],  w[3]);
            dst[1] = make_float4(w[4],  w[5],  w[6],  w[7]);
            dst[2] = make_float4(w[8],  w[9],  w[10], w[11]);
            dst[3] = make_float4(w[12], w[13], w[14], w[15]);
        }

        // ---- compose (t=0 is initialization, not a transition) ----
        const int t = t0 + s;
        if (t > 0) {
            const float up1   = eta * inv0;   // into k=1
            const float upm   = eta * invm;   // into k>=2
            const float dia0  = d0  * inv0;
            const float diam  = dm  * invm;
            const float dia15 = d15 * inv15;
            const float dnm   = RHO * invm;   // into k<=13
            const float dn14  = RHO * inv15;  // into k=14
            const float4* emv = reinterpret_cast<const float4*>(embase + (size_t)s * K_);
            const float4 e0 = __ldg(emv + 0), e1 = __ldg(emv + 1);
            const float4 e2 = __ldg(emv + 2), e3 = __ldg(emv + 3);
            const float ee[16] = {e0.x, e0.y, e0.z, e0.w, e1.x, e1.y, e1.z, e1.w,
                                  e2.x, e2.y, e2.z, e2.w, e3.x, e3.y, e3.z, e3.w};
            float rs_new = 0.0f, prev = 0.0f;
#pragma unroll
            for (int k = 0; k < 16; k++) {
                const float cur = m[k];
                const float nxt = (k < 15) ? m[k + 1] : 0.0f;
                const float up  = (k == 0) ? 0.0f : (k == 1 ? up1 : upm);
                const float di  = (k == 0) ? dia0 : (k == 15 ? dia15 : diam);
                const float dn  = (k >= 14) ? (k == 14 ? dn14 : 0.0f) : dnm;
                float v = prev * up + cur * di;
                v += nxt * dn;
                v += CLIPV * (rs - (prev + cur + nxt));   // background (clip-to-1e-10)
                v *= __expf(ee[k]);
                m[k] = v;
                rs_new += v;
                prev = cur;
            }
            rs = rs_new;
            if ((s & 7) == 7) {   // rescale every 8 steps (scale cancels later)
                float mx = m[0];
#pragma unroll
                for (int k = 1; k < 16; k++) mx = fmaxf(mx, m[k]);
#pragma unroll
                for (int o = 1; o < 16; o <<= 1)
                    mx = fmaxf(mx, __shfl_xor_sync(hm, mx, o, 16));
                const float sc = __fdividef(1.0f, mx);
#pragma unroll
                for (int k = 0; k < 16; k++) m[k] *= sc;
                rs *= sc;
            }
        }
    }

    // store chunk matrix column-major: [chunk][k][i] = M[i][k]
    float* dstM = &g_chunkM[chunk][0][0];
#pragma unroll
    for (int k = 0; k < 16; k++) dstM[k * 16 + i] = m[k];
}

// ---------------------------------------------------------------------------
// Phase 2: per-batch scan over chunk matrices. One warp per batch.
// ---------------------------------------------------------------------------
__global__ void k_scan()
{
    const int b    = blockIdx.x;
    const int lane = threadIdx.x;     // 32 lanes; upper half duplicates work
    const int k    = lane & 15;

    float v = (k == 0) ? 1.0f : 0.0f;   // alpha after t=0 is one-hot on state 0
    for (int j = 0; j < NCH; j++) {
        const float4* col = reinterpret_cast<const float4*>(&g_chunkM[b * NCH + j][k][0]);
        const float4 c0 = col[0], c1 = col[1], c2 = col[2], c3 = col[3];
        const float cc[16] = {c0.x, c0.y, c0.z, c0.w, c1.x, c1.y, c1.z, c1.w,
                              c2.x, c2.y, c2.z, c2.w, c3.x, c3.y, c3.z, c3.w};
        float acc = 0.0f;
#pragma unroll
        for (int q = 0; q < 16; q++)
            acc = fmaf(__shfl_sync(FULLM, v, q, 16), cc[q], acc);
        float z = acc;
#pragma unroll
        for (int o = 1; o < 16; o <<= 1) z += __shfl_xor_sync(FULLM, z, o, 16);
        v = acc / z;
        if (j + 1 < NCH && lane < 16) g_carry[b * NCH + j + 1][k] = v;
    }
}

// ---------------------------------------------------------------------------
// Phase 3: replay each chunk. 2 chunks per warp (half-warps), lane owns state k.
// ---------------------------------------------------------------------------
__global__ __launch_bounds__(128) void k_replay(
    const float* __restrict__ em, const float* __restrict__ bp,
    const float* __restrict__ msk, float* __restrict__ out)
{
    const int gwarp = (blockIdx.x * blockDim.x + threadIdx.x) >> 5;
    const int lane  = threadIdx.x & 31;
    const int k     = lane & 15;
    const int chunk = gwarp * 2 + (lane >> 4);
    if (chunk >= NCHUNKS) return;
    const unsigned hm = 0xffffu << (lane & 16);
    const int b  = chunk / NCH;
    const int j  = chunk - b * NCH;
    const int t0 = j * C_;
    const size_t bT = (size_t)b * T_;

    float* __restrict__ bel = out;
    float* __restrict__ lgb = out + OFF_LB;
    float* __restrict__ lgz = out + OFF_LZ;

    float alpha, lb;
    int s0;
    if (j == 0) {
        // t = 0: log_alpha0 = [0, -1e6, ...]; lj0 = la0 + em0; lZ0 = em0[0]
        const float em0  = __ldg(em + bT * K_ + k);
        const float em00 = __shfl_sync(hm, em0, 0, 16);
        const float m0   = __ldg(msk + bT);
        lb = (k == 0) ? 0.0f
                      : ((m0 > 0.5f) ? ((-1.0e6f + em0) - em00) : -1.0e6f);
        alpha = (k == 0) ? 1.0f : 0.0f;
        bel[bT * K_ + k] = alpha;         // exp(0)=1, exp(-1e6)=0
        lgb[bT * K_ + k] = lb;
        if (k == 0) lgz[bT] = m0 * em00;
        s0 = 1;
    } else {
        alpha = g_carry[chunk][k];
        lb = __logf(alpha);
        s0 = 0;
    }

    for (int s = s0; s < C_; s++) {
        const int t = t0 + s;
        const float emv = __ldg(em + (bT + t) * K_ + k);
        const float bpv = __ldg(bp + bT + t);
        const float mv  = __ldg(msk + bT + t);

        const float eta = fminf(fmaxf(0.02f + 0.33f * bpv, 0.001f), 0.95f);
        const float d0  = 1.0f - eta;
        const float dm  = fmaxf((1.0f - eta) - RHO, 0.01f);
        const float rs0  = fmaxf(d0 + eta, 1e-8f);
        const float rsm  = fmaxf((RHO + dm) + eta, 1e-8f);
        const float rs15 = fmaxf(RHO + (1.0f - RHO), 1e-8f);
        const float inv0  = __fdividef(1.0f, rs0);
        const float invm  = __fdividef(1.0f, rsm);
        const float inv15 = __fdividef(1.0f, rs15);

        // incoming transition coefficients for state k
        const float a_up = eta * ((k == 1) ? inv0 : invm);                 // from k-1
        const float a_di = (k == 0) ? d0 * inv0
                          : (k == 15 ? (1.0f - RHO) * inv15 : dm * invm);  // from k
        const float a_dn = RHO * ((k == 14) ? inv15 : invm);               // from k+1

        const float am1 = __shfl_up_sync(hm, alpha, 1, 16);
        const float ap1 = __shfl_down_sync(hm, alpha, 1, 16);
        const float c_m1 = (k > 0)  ? am1 : 0.0f;
        const float c_p1 = (k < 15) ? ap1 : 0.0f;

        float pred = c_m1 * a_up + alpha * a_di;
        pred += c_p1 * a_dn;
        pred += CLIPV * (1.0f - (c_m1 + alpha + c_p1));   // background, S=1
        const float lj = pred * __expf(emv);

        float z = lj;
#pragma unroll
        for (int o = 1; o < 16; o <<= 1) z += __shfl_xor_sync(hm, z, o, 16);

        const float lZ  = __logf(z);
        const float an  = __fdividef(lj, z);
        const float lbn = __logf(an);
        const bool mm = (mv > 0.5f);
        alpha = mm ? an  : alpha;
        lb    = mm ? lbn : lb;

        bel[(bT + t) * K_ + k] = alpha;
        lgb[(bT + t) * K_ + k] = lb;
        if (k == 0) lgz[bT + t] = mv * lZ;
    }
}

extern "C" void kernel_launch(void* const* d_in, const int* in_sizes, int n_in,
                              void* d_out, int out_size)
{
    const float* em  = (const float*)d_in[0];   // emission_log_probs [B,T,K]
    const float* bp  = (const float*)d_in[1];   // boundary_probs   [B,T]
    const float* msk = (const float*)d_in[2];   // mask             [B,T]
    float* out = (float*)d_out;

    k_chunkmats<<<NCHUNKS / 8, 128>>>(em, bp, out);   // 256 blocks x 4 warps x 2 chunks
    k_scan<<<B_, 32>>>();
    k_replay<<<NCHUNKS / 8, 128>>>(em, bp, msk, out);
}

// round 4
// speedup vs baseline: 1.2971x; 1.2971x over previous
#include <cuda_runtime.h>
#include <cstdint>

// NeuralHMM forward, B=32, T=4096, K=16 — 3-phase chunked linear-space scan.
// C=32 timesteps/chunk -> 4096 chunks (2 per warp via half-warps), 512 blocks.

#define FULLM 0xffffffffu

constexpr int B_ = 32, T_ = 4096, K_ = 16, C_ = 32, NCH = T_ / C_;   // NCH = 128
constexpr int NCHUNKS = B_ * NCH;                                     // 4096
constexpr float RHO = 0.001f;
constexpr float CLIPV = 1e-10f;

__device__ __align__(16) float g_chunkM[NCHUNKS][K_][K_]; // [chunk][k][i] = M[i][k]
__device__ __align__(16) float g_carry[NCHUNKS][K_];      // UNNORMALIZED alpha entering chunk j>=1

constexpr size_t N_BTK = (size_t)B_ * T_ * K_;
constexpr size_t N_BT  = (size_t)B_ * T_;
constexpr size_t OFF_LB = N_BTK;
constexpr size_t OFF_LZ = 2 * N_BTK;
constexpr size_t OFF_A  = 2 * N_BTK + N_BT;

// ---------------------------------------------------------------------------
// Phase 1: chunk transfer matrices + A output. 2 chunks/warp, lane owns row i.
// ---------------------------------------------------------------------------
__global__ __launch_bounds__(128) void k_chunkmats(
    const float* __restrict__ em, const float* __restrict__ bp,
    float* __restrict__ out)
{
    const int gwarp = (blockIdx.x * blockDim.x + threadIdx.x) >> 5;
    const int lane  = threadIdx.x & 31;
    const int i     = lane & 15;
    const int chunk = gwarp * 2 + (lane >> 4);
    const unsigned hm = 0xffffu << (lane & 16);
    const int b  = chunk >> 7;           // /NCH
    const int j  = chunk & (NCH - 1);
    const int t0 = j * C_;
    const size_t bt0 = (size_t)b * T_ + t0;

    float* __restrict__ Abase = out + OFF_A + bt0 * (size_t)(K_ * K_);
    const float* __restrict__ embase = em + bt0 * K_;

    // --- A-write one-hot masks over an 8-float window covering cols i-1..i+1 ---
    int g_lo = (i <= 1) ? 0 : ((i - 1) >> 2);
    if (g_lo > 2) g_lo = 2;
    const int p = (i == 0) ? -1 : (i - 1) - g_lo * 4;
    float mr[8], md[8], me[8];
#pragma unroll
    for (int c = 0; c < 8; c++) {
        mr[c] = (c == p)     ? 1.0f : 0.0f;
        md[c] = (c == p + 1) ? 1.0f : 0.0f;
        me[c] = (c == p + 2) ? 1.0f : 0.0f;
    }
    const int zg0 = (g_lo + 2) & 3, zg1 = (g_lo + 3) & 3;
    const float4 zero4 = make_float4(0.f, 0.f, 0.f, 0.f);

    // --- upfront bp (32 values per chunk via 2 regs + shfl) ---
    const float bpA = __ldg(bp + bt0 + i);
    const float bpB = __ldg(bp + bt0 + 16 + i);

    // --- em ring prefetch (lane's own k=i element), depth 4 ---
    float er[4];
#pragma unroll
    for (int u = 0; u < 4; u++) er[u] = __ldg(embase + u * K_ + i);

    float m[K_];
#pragma unroll
    for (int k = 0; k < K_; k++) m[k] = (k == i) ? 1.0f : 0.0f;
    float rs = 1.0f;

#pragma unroll 4
    for (int s = 0; s < C_; s++) {
        const float emraw = er[s & 3];
        if (s + 4 < C_) er[s & 3] = __ldg(embase + (s + 4) * K_ + i);

        const float bpv = __shfl_sync(hm, (s < 16) ? bpA : bpB, s & 15, 16);
        const float eta = fminf(fmaxf(0.02f + 0.33f * bpv, 0.001f), 0.95f);
        const float d0  = 1.0f - eta;
        const float dm  = fmaxf((1.0f - eta) - RHO, 0.01f);
        const float d15 = 1.0f - RHO;
        const float inv0  = __fdividef(1.0f, fmaxf(d0 + eta, 1e-8f));
        const float invm  = __fdividef(1.0f, fmaxf((RHO + dm) + eta, 1e-8f));
        const float inv15 = __fdividef(1.0f, fmaxf(RHO + d15, 1e-8f));

        // ---- A row i write ----
        {
            const float invr = (i == 0) ? inv0 : (i == 15 ? inv15 : invm);
            const float dv = ((i == 0) ? d0 : (i == 15 ? d15 : dm)) * invr;
            const float ev = eta * invr;
            const float rv = RHO * invr;
            float w[8];
#pragma unroll
            for (int c = 0; c < 8; c++)
                w[c] = fmaf(mr[c], rv, fmaf(md[c], dv, me[c] * ev));
            float4* dst = reinterpret_cast<float4*>(Abase + (size_t)s * 256 + i * 16);
            __stcs(dst + zg0, zero4);
            __stcs(dst + zg1, zero4);
            __stcs(dst + g_lo,     make_float4(w[0], w[1], w[2], w[3]));
            __stcs(dst + g_lo + 1, make_float4(w[4], w[5], w[6], w[7]));
        }

        // ---- compose (t=0 is init, not a transition) ----
        if (t0 + s > 0) {
            const float e_own = __expf(emraw);
            const float up1   = eta * inv0;
            const float upm   = eta * invm;
            const float dia0  = d0  * inv0;
            const float diam  = dm  * invm;
            const float dia15 = d15 * inv15;
            const float dnm   = RHO * invm;
            const float dn14  = RHO * inv15;
            float rs_new = 0.0f, prev = 0.0f;
#pragma unroll
            for (int k = 0; k < 16; k++) {
                const float cur = m[k];
                const float nxt = (k < 15) ? m[k + 1] : 0.0f;
                const float up  = (k == 0) ? 0.0f : (k == 1 ? up1 : upm);
                const float di  = (k == 0) ? dia0 : (k == 15 ? dia15 : diam);
                const float dn  = (k >= 14) ? (k == 14 ? dn14 : 0.0f) : dnm;
                float v = prev * up + cur * di;
                v += nxt * dn;
                v = fmaf(CLIPV, rs - (prev + cur + nxt), v);   // clip background
                v *= __shfl_sync(hm, e_own, k, 16);
                m[k] = v;
                rs_new += v;
                prev = cur;
            }
            rs = rs_new;
            if ((s & 7) == 7) {
                float mx = m[0];
#pragma unroll
                for (int k = 1; k < 16; k++) mx = fmaxf(mx, m[k]);
#pragma unroll
                for (int o = 1; o < 16; o <<= 1)
                    mx = fmaxf(mx, __shfl_xor_sync(hm, mx, o, 16));
                const float sc = __fdividef(1.0f, mx);
#pragma unroll
                for (int k = 0; k < 16; k++) m[k] *= sc;
                rs *= sc;
            }
        }
    }

    float* dstM = &g_chunkM[chunk][0][0];
#pragma unroll
    for (int k = 0; k < 16; k++) dstM[k * 16 + i] = m[k];
}

// ---------------------------------------------------------------------------
// Phase 2: per-batch scan over chunk matrices (one warp per batch).
// No per-hop normalization (scale-invariant); rescale by max every 8 hops.
// Carries are stored UNNORMALIZED; phase 3 normalizes on entry.
// ---------------------------------------------------------------------------
__global__ void k_scan()
{
    const int b    = blockIdx.x;
    const int lane = threadIdx.x;
    const int k    = lane & 15;

    float v = (k == 0) ? 1.0f : 0.0f;

    const float4* col = reinterpret_cast<const float4*>(&g_chunkM[b * NCH][k][0]);
    float4 c0 = col[0], c1 = col[1], c2 = col[2], c3 = col[3];

    for (int j = 0; j < NCH; j++) {
        float4 n0, n1, n2, n3;
        if (j + 1 < NCH) {
            const float4* ncol = reinterpret_cast<const float4*>(&g_chunkM[b * NCH + j + 1][k][0]);
            n0 = ncol[0]; n1 = ncol[1]; n2 = ncol[2]; n3 = ncol[3];
        } else {
            n0 = n1 = n2 = n3 = make_float4(0.f, 0.f, 0.f, 0.f);
        }
        float a0 = 0.f, a1 = 0.f, a2 = 0.f, a3 = 0.f;
        a0 = fmaf(__shfl_sync(FULLM, v, 0,  16), c0.x, a0);
        a0 = fmaf(__shfl_sync(FULLM, v, 1,  16), c0.y, a0);
        a0 = fmaf(__shfl_sync(FULLM, v, 2,  16), c0.z, a0);
        a0 = fmaf(__shfl_sync(FULLM, v, 3,  16), c0.w, a0);
        a1 = fmaf(__shfl_sync(FULLM, v, 4,  16), c1.x, a1);
        a1 = fmaf(__shfl_sync(FULLM, v, 5,  16), c1.y, a1);
        a1 = fmaf(__shfl_sync(FULLM, v, 6,  16), c1.z, a1);
        a1 = fmaf(__shfl_sync(FULLM, v, 7,  16), c1.w, a1);
        a2 = fmaf(__shfl_sync(FULLM, v, 8,  16), c2.x, a2);
        a2 = fmaf(__shfl_sync(FULLM, v, 9,  16), c2.y, a2);
        a2 = fmaf(__shfl_sync(FULLM, v, 10, 16), c2.z, a2);
        a2 = fmaf(__shfl_sync(FULLM, v, 11, 16), c2.w, a2);
        a3 = fmaf(__shfl_sync(FULLM, v, 12, 16), c3.x, a3);
        a3 = fmaf(__shfl_sync(FULLM, v, 13, 16), c3.y, a3);
        a3 = fmaf(__shfl_sync(FULLM, v, 14, 16), c3.z, a3);
        a3 = fmaf(__shfl_sync(FULLM, v, 15, 16), c3.w, a3);
        v = (a0 + a1) + (a2 + a3);

        if (j + 1 < NCH && lane < 16) g_carry[b * NCH + j + 1][k] = v;

        if ((j & 7) == 7) {
            float mx = v;
#pragma unroll
            for (int o = 1; o < 16; o <<= 1)
                mx = fmaxf(mx, __shfl_xor_sync(FULLM, mx, o, 16));
            v *= __fdividef(1.0f, mx);
        }
        c0 = n0; c1 = n1; c2 = n2; c3 = n3;
    }
}

// ---------------------------------------------------------------------------
// Phase 3: replay each chunk. 2 chunks/warp, lane owns state k.
// Carry is normalized ON ENTRY (alpha /= S), so inside the loop the incoming
// alpha always sums to 1 — this makes lZ = log(z) exact (R3 bug fix).
// ---------------------------------------------------------------------------
__global__ __launch_bounds__(128) void k_replay(
    const float* __restrict__ em, const float* __restrict__ bp,
    const float* __restrict__ msk, float* __restrict__ out)
{
    const int gwarp = (blockIdx.x * blockDim.x + threadIdx.x) >> 5;
    const int lane  = threadIdx.x & 31;
    const int k     = lane & 15;
    const int chunk = gwarp * 2 + (lane >> 4);
    const unsigned hm = 0xffffu << (lane & 16);
    const int b  = chunk >> 7;
    const int j  = chunk & (NCH - 1);
    const int t0 = j * C_;
    const size_t bt0 = (size_t)b * T_ + t0;

    float* __restrict__ bel = out;
    float* __restrict__ lgb = out + OFF_LB;
    float* __restrict__ lgz = out + OFF_LZ;

    const float* __restrict__ embase = em + bt0 * K_;

    const float bpv0 = __ldg(bp  + bt0 + k);
    const float bpv1 = __ldg(bp  + bt0 + 16 + k);
    const float mv0  = __ldg(msk + bt0 + k);
    const float mv1  = __ldg(msk + bt0 + 16 + k);

    float er[4];
#pragma unroll
    for (int u = 0; u < 4; u++) er[u] = __ldg(embase + u * K_ + k);

    float alpha;
    if (j == 0) {
        alpha = (k == 0) ? 1.0f : 0.0f;
    } else {
        alpha = g_carry[chunk][k];
        float ss = alpha;
#pragma unroll
        for (int o = 1; o < 16; o <<= 1) ss += __shfl_xor_sync(hm, ss, o, 16);
        alpha *= __fdividef(1.0f, ss);     // normalize carry: sum(alpha) == 1
    }

#pragma unroll 4
    for (int s = 0; s < C_; s++) {
        const float emv = er[s & 3];
        if (s + 4 < C_) er[s & 3] = __ldg(embase + (s + 4) * K_ + k);

        const size_t t = bt0 + s;
        const float bpv = __shfl_sync(hm, (s < 16) ? bpv0 : bpv1, s & 15, 16);
        const float mv  = __shfl_sync(hm, (s < 16) ? mv0  : mv1,  s & 15, 16);

        if (s == 0 && j == 0) {
            const float em00 = __shfl_sync(hm, emv, 0, 16);
            const float lb0 = (k == 0) ? 0.0f
                          : ((mv > 0.5f) ? ((-1.0e6f + emv) - em00) : -1.0e6f);
            bel[t * K_ + k] = alpha;
            lgb[t * K_ + k] = lb0;
            if (k == 0) lgz[t] = mv * em00;
            continue;
        }

        const float eta = fminf(fmaxf(0.02f + 0.33f * bpv, 0.001f), 0.95f);
        const float d0  = 1.0f - eta;
        const float dm  = fmaxf((1.0f - eta) - RHO, 0.01f);
        const float inv0  = __fdividef(1.0f, fmaxf(d0 + eta, 1e-8f));
        const float invm  = __fdividef(1.0f, fmaxf((RHO + dm) + eta, 1e-8f));
        const float inv15 = __fdividef(1.0f, fmaxf(RHO + (1.0f - RHO), 1e-8f));

        const float a_up = eta * ((k == 1) ? inv0 : invm);
        const float a_di = (k == 0) ? d0 * inv0
                          : (k == 15 ? (1.0f - RHO) * inv15 : dm * invm);
        const float a_dn = RHO * ((k == 14) ? inv15 : invm);

        const float am1 = __shfl_up_sync(hm, alpha, 1, 16);
        const float ap1 = __shfl_down_sync(hm, alpha, 1, 16);
        const float c_m1 = (k > 0)  ? am1 : 0.0f;
        const float c_p1 = (k < 15) ? ap1 : 0.0f;

        float pred = c_m1 * a_up + alpha * a_di;
        pred += c_p1 * a_dn;
        pred = fmaf(CLIPV, 1.0f - ((c_m1 + alpha) + c_p1), pred);  // sum(alpha)==1
        const float lj  = pred * __expf(emv);
        const float llj = __logf(lj);

        float z = lj;
#pragma unroll
        for (int o = 1; o < 16; o <<= 1) z += __shfl_xor_sync(hm, z, o, 16);

        const float lZ  = __logf(z);
        const float an  = __fdividef(lj, z);
        const float lbn = llj - lZ;

        const bool mm = (mv > 0.5f);
        const float lbprev = __logf(alpha);   // alpha is normalized
        alpha = mm ? an : alpha;

        bel[t * K_ + k] = alpha;
        lgb[t * K_ + k] = mm ? lbn : lbprev;
        if (k == 0) lgz[t] = mv * lZ;
    }
}

extern "C" void kernel_launch(void* const* d_in, const int* in_sizes, int n_in,
                              void* d_out, int out_size)
{
    const float* em  = (const float*)d_in[0];
    const float* bp  = (const float*)d_in[1];
    const float* msk = (const float*)d_in[2];
    float* out = (float*)d_out;

    k_chunkmats<<<NCHUNKS / 8, 128>>>(em, bp, out);   // 512 blocks
    k_scan<<<B_, 32>>>();
    k_replay<<<NCHUNKS / 8, 128>>>(em, bp, msk, out); // 512 blocks
}